// round 1
// baseline (speedup 1.0000x reference)
#include <cuda_runtime.h>

#define B_TOTAL   1024
#define T_STEPS   512
#define HID       64
#define NGATE     256
#define NB        8
#define NCTA      128
#define NTHREADS  256

typedef unsigned long long u64;

// Packed f32x2 FMA (Blackwell sm_103a): d = a*b + c elementwise on 2 floats.
__device__ __forceinline__ u64 ffma2(u64 a, u64 b, u64 c) {
    u64 d;
    asm("fma.rn.f32x2 %0, %1, %2, %3;" : "=l"(d) : "l"(a), "l"(b), "l"(c));
    return d;
}

__device__ __forceinline__ float hadd2(u64 v) {
    float lo, hi;
    asm("mov.b64 {%0, %1}, %2;" : "=f"(lo), "=f"(hi) : "l"(v));
    return lo + hi;
}

__device__ __forceinline__ float sigf(float x) {
    return __fdividef(1.0f, 1.0f + __expf(-x));
}

// Safe fast tanh: works for all finite x (no inf/inf).
__device__ __forceinline__ float tanhf_(float x) {
    float e = __expf(-2.0f * fabsf(x));
    float r = __fdividef(1.0f - e, 1.0f + e);
    return copysignf(r, x);
}

// Dynamic SMEM layout (bytes):
//   [0      .. 65536)  wih1p_s : u64 [32 kp][256 g]   (W_ih1, k-major packed pairs)
//   [65536  .. 81920)  x_s     : f32 [512 t][8 b]
//   [81920  .. 83968)  h0_s    : f32 [8 b][64 u]
//   [83968  .. 86016)  h1_s    : f32 [8 b][64 u]
//   [86016  .. 94208)  g0_s    : f32 [8 b][256 g]
//   [94208  ..102400)  g1_s    : f32 [8 b][256 g]
//   [102400 ..102656)  wfc_s   : f32 [64]
#define SMEM_BYTES 102656

__global__ void __launch_bounds__(NTHREADS, 1)
lstm2_kernel(const float* __restrict__ x,
             const float* __restrict__ W_ih0, const float* __restrict__ W_hh0,
             const float* __restrict__ b_ih0, const float* __restrict__ b_hh0,
             const float* __restrict__ W_ih1, const float* __restrict__ W_hh1,
             const float* __restrict__ b_ih1, const float* __restrict__ b_hh1,
             const float* __restrict__ W_fc,  const float* __restrict__ b_fc,
             float* __restrict__ out)
{
    extern __shared__ char smem_raw[];
    u64*   wih1p_s = (u64*)  (smem_raw);
    float* x_s     = (float*)(smem_raw + 65536);
    float* h0_s    = (float*)(smem_raw + 81920);
    float* h1_s    = (float*)(smem_raw + 83968);
    float* g0_s    = (float*)(smem_raw + 86016);
    float* g1_s    = (float*)(smem_raw + 94208);
    float* wfc_s   = (float*)(smem_raw + 102400);

    const int tid   = threadIdx.x;
    const int g     = tid;                 // gate row owned by this thread
    const int bbase = blockIdx.x * NB;

    // ---- per-thread recurrent weight rows, packed as f32x2 pairs in regs ----
    u64 whh0p[32], whh1p[32];
    {
        const ulonglong2* p0 = (const ulonglong2*)(W_hh0 + (size_t)g * HID);
        const ulonglong2* p1 = (const ulonglong2*)(W_hh1 + (size_t)g * HID);
#pragma unroll
        for (int j = 0; j < 16; j++) {
            ulonglong2 v0 = p0[j]; whh0p[2*j] = v0.x; whh0p[2*j+1] = v0.y;
            ulonglong2 v1 = p1[j]; whh1p[2*j] = v1.x; whh1p[2*j+1] = v1.y;
        }
    }
    const float b0v   = b_ih0[g] + b_hh0[g];
    const float b1v   = b_ih1[g] + b_hh1[g];
    const float wih0v = W_ih0[g];          // D == 1

    // ---- stage W_ih1 into SMEM, k-major packed pairs: wih1p_s[kp*256 + g] ----
    for (int idx = tid; idx < NGATE * 32; idx += NTHREADS) {
        int gg = idx >> 5, kp = idx & 31;
        wih1p_s[kp * NGATE + gg] = ((const u64*)W_ih1)[gg * 32 + kp];
    }
    // ---- stage x tile, transposed to [t][b] ----
    for (int idx = tid; idx < NB * T_STEPS; idx += NTHREADS) {
        int b = idx >> 9, t = idx & (T_STEPS - 1);
        x_s[t * NB + b] = x[(size_t)(bbase + b) * T_STEPS + t];
    }
    if (tid < HID) wfc_s[tid] = W_fc[tid];
    for (int idx = tid; idx < NB * HID; idx += NTHREADS) { h0_s[idx] = 0.0f; h1_s[idx] = 0.0f; }
    __syncthreads();

    // activation-phase ownership: 512 (b,u) pairs -> 2 per thread
    const int bA = tid >> 6, uA = tid & 63;
    const int bB = bA + 4;
    float c0A = 0.0f, c0B = 0.0f, c1A = 0.0f, c1B = 0.0f;

    for (int t = 0; t < T_STEPS; t++) {
        u64 acc[NB];

        // ============ layer 0: gates[b][g] = b0 + wih0*x + W_hh0[g,:] . h0[b,:] ============
#pragma unroll
        for (int b = 0; b < NB; b++) acc[b] = 0ull;
#pragma unroll
        for (int kc = 0; kc < 16; kc++) {
            u64 w0 = whh0p[2*kc], w1 = whh0p[2*kc+1];
#pragma unroll
            for (int b = 0; b < NB; b++) {
                ulonglong2 h2 = *(const ulonglong2*)(h0_s + b * HID + kc * 4);
                acc[b] = ffma2(w0, h2.x, acc[b]);
                acc[b] = ffma2(w1, h2.y, acc[b]);
            }
        }
#pragma unroll
        for (int b = 0; b < NB; b++) {
            float a = hadd2(acc[b]);
            a = fmaf(wih0v, x_s[t * NB + b], a) + b0v;
            g0_s[b * NGATE + g] = a;
        }
        __syncthreads();   // S1: gates0 ready

        // ============ act 0 ============
        {
            float xi = g0_s[bA * NGATE +       uA];
            float xf = g0_s[bA * NGATE +  64 + uA];
            float xg = g0_s[bA * NGATE + 128 + uA];
            float xo = g0_s[bA * NGATE + 192 + uA];
            float ii = sigf(xi), ff = sigf(xf), gv = tanhf_(xg), oo = sigf(xo);
            c0A = ff * c0A + ii * gv;
            h0_s[bA * HID + uA] = oo * tanhf_(c0A);

            xi = g0_s[bB * NGATE +       uA];
            xf = g0_s[bB * NGATE +  64 + uA];
            xg = g0_s[bB * NGATE + 128 + uA];
            xo = g0_s[bB * NGATE + 192 + uA];
            ii = sigf(xi); ff = sigf(xf); gv = tanhf_(xg); oo = sigf(xo);
            c0B = ff * c0B + ii * gv;
            h0_s[bB * HID + uA] = oo * tanhf_(c0B);
        }
        __syncthreads();   // S2: h0 updated

        // ============ layer 1: gates = b1 + W_ih1 . h0 + W_hh1 . h1 ============
#pragma unroll
        for (int b = 0; b < NB; b++) acc[b] = 0ull;
#pragma unroll
        for (int kc = 0; kc < 16; kc++) {
            u64 w0 = wih1p_s[(2*kc)   * NGATE + g];
            u64 w1 = wih1p_s[(2*kc+1) * NGATE + g];
#pragma unroll
            for (int b = 0; b < NB; b++) {
                ulonglong2 h2 = *(const ulonglong2*)(h0_s + b * HID + kc * 4);
                acc[b] = ffma2(w0, h2.x, acc[b]);
                acc[b] = ffma2(w1, h2.y, acc[b]);
            }
        }
#pragma unroll
        for (int kc = 0; kc < 16; kc++) {
            u64 w0 = whh1p[2*kc], w1 = whh1p[2*kc+1];
#pragma unroll
            for (int b = 0; b < NB; b++) {
                ulonglong2 h2 = *(const ulonglong2*)(h1_s + b * HID + kc * 4);
                acc[b] = ffma2(w0, h2.x, acc[b]);
                acc[b] = ffma2(w1, h2.y, acc[b]);
            }
        }
#pragma unroll
        for (int b = 0; b < NB; b++) {
            g1_s[b * NGATE + g] = hadd2(acc[b]) + b1v;
        }
        __syncthreads();   // S3: gates1 ready

        // ============ act 1 (no trailing barrier needed: next reads of h1_s/g1_s
        //              occur only after S1/S2/S3 of the next iteration) ============
        {
            float xi = g1_s[bA * NGATE +       uA];
            float xf = g1_s[bA * NGATE +  64 + uA];
            float xg = g1_s[bA * NGATE + 128 + uA];
            float xo = g1_s[bA * NGATE + 192 + uA];
            float ii = sigf(xi), ff = sigf(xf), gv = tanhf_(xg), oo = sigf(xo);
            c1A = ff * c1A + ii * gv;
            h1_s[bA * HID + uA] = oo * tanhf_(c1A);

            xi = g1_s[bB * NGATE +       uA];
            xf = g1_s[bB * NGATE +  64 + uA];
            xg = g1_s[bB * NGATE + 128 + uA];
            xo = g1_s[bB * NGATE + 192 + uA];
            ii = sigf(xi); ff = sigf(xf); gv = tanhf_(xg); oo = sigf(xo);
            c1B = ff * c1B + ii * gv;
            h1_s[bB * HID + uA] = oo * tanhf_(c1B);
        }
    }
    __syncthreads();

    // ---- output: out[b] = h0f[b].Wfc + bfc ; out[1024+b] = h1f[b].Wfc + bfc ----
    if (tid < 2 * NB) {
        int b = tid & (NB - 1);
        const float* hp = (tid < NB) ? h0_s : h1_s;
        float s = b_fc[0];
#pragma unroll
        for (int u = 0; u < HID; u++) s = fmaf(hp[b * HID + u], wfc_s[u], s);
        out[(tid < NB ? 0 : B_TOTAL) + bbase + b] = s;
    }
}

extern "C" void kernel_launch(void* const* d_in, const int* in_sizes, int n_in,
                              void* d_out, int out_size) {
    const float* x     = (const float*)d_in[0];
    const float* W_ih0 = (const float*)d_in[1];
    const float* W_hh0 = (const float*)d_in[2];
    const float* b_ih0 = (const float*)d_in[3];
    const float* b_hh0 = (const float*)d_in[4];
    const float* W_ih1 = (const float*)d_in[5];
    const float* W_hh1 = (const float*)d_in[6];
    const float* b_ih1 = (const float*)d_in[7];
    const float* b_hh1 = (const float*)d_in[8];
    const float* W_fc  = (const float*)d_in[9];
    const float* b_fc  = (const float*)d_in[10];
    float* out = (float*)d_out;

    cudaFuncSetAttribute(lstm2_kernel,
                         cudaFuncAttributeMaxDynamicSharedMemorySize, SMEM_BYTES);
    lstm2_kernel<<<NCTA, NTHREADS, SMEM_BYTES>>>(
        x, W_ih0, W_hh0, b_ih0, b_hh0,
        W_ih1, W_hh1, b_ih1, b_hh1, W_fc, b_fc, out);
}